// round 1
// baseline (speedup 1.0000x reference)
#include <cuda_runtime.h>
#include <mma.h>

using namespace nvcuda;

#define B_SZ 8
#define T_SZ 4096
#define D_SZ 1024
#define H_SZ 1024
#define M_TOT (B_SZ * T_SZ)   // 32768
#define NC 32                  // chunks along T
#define CL 128                 // chunk length (NC*CL = T_SZ)

// Scratch (static __device__ arrays — no allocation in kernel_launch)
__device__ float g_k [M_TOT * H_SZ];   // k pre-bias, then overwritten with a = sigmoid(-k)
__device__ float g_th[M_TOT * H_SZ];   // tilde_h pre-bias, then overwritten with b = sigmoid(k)*g(th)
__device__ float g_A   [B_SZ * NC * H_SZ];
__device__ float g_Bc  [B_SZ * NC * H_SZ];
__device__ float g_hini[B_SZ * NC * H_SZ];

// ---------------------------------------------------------------------------
// GEMM: C[m,n] = sum_d x[m,d] * W[n,d]   (TN: both operands K-contiguous)
// CTA tile 128x64x32, 8 warps, warp tile 32x32 via 2x2 wmma m16n16k8 tf32.
// Virtual N = 2048: first half -> Wz -> g_k, second half -> Wh -> g_th.
// ---------------------------------------------------------------------------
#define BM 128
#define BN 64
#define BK 32
#define LDS (BK + 8)   // 40 floats: 160B rows (16B-aligned for wmma ldm)

__global__ __launch_bounds__(256) void gemm_kernel(const float* __restrict__ x,
                                                   const float* __restrict__ Wz,
                                                   const float* __restrict__ Wh)
{
    __shared__ __align__(16) float As[BM][LDS];
    __shared__ __align__(16) float Bs[BN][LDS];

    const int tid = threadIdx.x;
    const int m0  = blockIdx.y * BM;
    const int n_global = blockIdx.x * BN;

    const float* W;
    float* outbuf;
    int ncol;
    if (n_global < H_SZ) { W = Wz; outbuf = g_k;  ncol = n_global; }
    else                 { W = Wh; outbuf = g_th; ncol = n_global - H_SZ; }

    const int warpId = tid >> 5;
    const int wm = warpId & 3;   // 0..3  (M)
    const int wn = warpId >> 2;  // 0..1  (N)

    wmma::fragment<wmma::accumulator, 16, 16, 8, float> acc[2][2];
    #pragma unroll
    for (int i = 0; i < 2; i++)
        #pragma unroll
        for (int j = 0; j < 2; j++)
            wmma::fill_fragment(acc[i][j], 0.0f);

    for (int k0 = 0; k0 < D_SZ; k0 += BK) {
        // Load A tile: 128x32 floats = 1024 float4, 4 per thread
        #pragma unroll
        for (int j = 0; j < 4; j++) {
            int idx = tid + j * 256;
            int r = idx >> 3, kq = idx & 7;
            float4 v = *reinterpret_cast<const float4*>(
                &x[(size_t)(m0 + r) * D_SZ + k0 + kq * 4]);
            As[r][kq * 4 + 0] = v.x; As[r][kq * 4 + 1] = v.y;
            As[r][kq * 4 + 2] = v.z; As[r][kq * 4 + 3] = v.w;
        }
        // Load B tile: 64x32 floats = 512 float4, 2 per thread
        #pragma unroll
        for (int j = 0; j < 2; j++) {
            int idx = tid + j * 256;
            int r = idx >> 3, kq = idx & 7;
            float4 v = *reinterpret_cast<const float4*>(
                &W[(size_t)(ncol + r) * D_SZ + k0 + kq * 4]);
            Bs[r][kq * 4 + 0] = v.x; Bs[r][kq * 4 + 1] = v.y;
            Bs[r][kq * 4 + 2] = v.z; Bs[r][kq * 4 + 3] = v.w;
        }
        __syncthreads();

        #pragma unroll
        for (int ks = 0; ks < BK; ks += 8) {
            wmma::fragment<wmma::matrix_a, 16, 16, 8, wmma::precision::tf32, wmma::row_major> af[2];
            wmma::fragment<wmma::matrix_b, 16, 16, 8, wmma::precision::tf32, wmma::col_major> bf[2];
            #pragma unroll
            for (int i = 0; i < 2; i++) {
                wmma::load_matrix_sync(af[i], &As[wm * 32 + i * 16][ks], LDS);
                #pragma unroll
                for (int t = 0; t < af[i].num_elements; t++)
                    af[i].x[t] = wmma::__float_to_tf32(af[i].x[t]);
            }
            #pragma unroll
            for (int j = 0; j < 2; j++) {
                wmma::load_matrix_sync(bf[j], &Bs[wn * 32 + j * 16][ks], LDS);
                #pragma unroll
                for (int t = 0; t < bf[j].num_elements; t++)
                    bf[j].x[t] = wmma::__float_to_tf32(bf[j].x[t]);
            }
            #pragma unroll
            for (int i = 0; i < 2; i++)
                #pragma unroll
                for (int j = 0; j < 2; j++)
                    wmma::mma_sync(acc[i][j], af[i], bf[j], acc[i][j]);
        }
        __syncthreads();
    }

    #pragma unroll
    for (int i = 0; i < 2; i++)
        #pragma unroll
        for (int j = 0; j < 2; j++) {
            int mrow = m0 + wm * 32 + i * 16;
            int nc   = ncol + wn * 32 + j * 16;
            wmma::store_matrix_sync(&outbuf[(size_t)mrow * H_SZ + nc],
                                    acc[i][j], H_SZ, wmma::mem_row_major);
        }
}

// ---------------------------------------------------------------------------
// Elementwise: add bias, compute gate quantities in-place.
//   a = 1 - sigmoid(k) = sigmoid(-k)          -> g_k
//   b = sigmoid(k) * g(th)                    -> g_th
//   g(th) = th>=0 ? th+0.5 : sigmoid(th)
// ---------------------------------------------------------------------------
__global__ __launch_bounds__(256) void ew_kernel(const float* __restrict__ bz,
                                                 const float* __restrict__ bh)
{
    size_t idx = (size_t)blockIdx.x * 256 + threadIdx.x;
    int h = (int)(idx & (H_SZ - 1));
    float k  = g_k[idx]  + bz[h];
    float th = g_th[idx] + bh[h];

    // stable sigmoid pair
    float em  = __expf(-fabsf(k));
    float inv = 1.0f / (1.0f + em);
    float z, a;
    if (k >= 0.0f) { z = inv;      a = em * inv; }
    else           { z = em * inv; a = inv;      }

    float g;
    if (th >= 0.0f) g = th + 0.5f;
    else            g = 1.0f / (1.0f + __expf(-th));   // sigmoid(th), th<0 safe

    g_k[idx]  = a;
    g_th[idx] = z * g;
}

// ---------------------------------------------------------------------------
// Chunked scan: h[t] = a[t]*h[t-1] + b[t], h[-1] = 0
// ---------------------------------------------------------------------------
__global__ __launch_bounds__(256) void scan1_kernel()
{
    int idx = blockIdx.x * 256 + threadIdx.x;   // 0 .. B*NC*H-1 = 262143
    int h  = idx & (H_SZ - 1);
    int bc = idx >> 10;          // b*NC + c
    int c  = bc & (NC - 1);
    int b  = bc >> 5;
    size_t base = ((size_t)b * T_SZ + (size_t)c * CL) * H_SZ + h;

    float A = 1.0f, acc = 0.0f;
    #pragma unroll 4
    for (int t = 0; t < CL; t++) {
        float a  = g_k [base + (size_t)t * H_SZ];
        float bb = g_th[base + (size_t)t * H_SZ];
        A *= a;
        acc = fmaf(a, acc, bb);
    }
    g_A [idx] = A;
    g_Bc[idx] = acc;
}

__global__ __launch_bounds__(256) void scan2_kernel()
{
    int idx = blockIdx.x * 256 + threadIdx.x;   // 0 .. B*H-1 = 8191
    int h = idx & (H_SZ - 1);
    int b = idx >> 10;
    float carry = 0.0f;
    #pragma unroll
    for (int c = 0; c < NC; c++) {
        int j = (b * NC + c) * H_SZ + h;
        g_hini[j] = carry;
        carry = fmaf(g_A[j], carry, g_Bc[j]);
    }
}

__global__ __launch_bounds__(256) void scan3_kernel(float* __restrict__ out)
{
    int idx = blockIdx.x * 256 + threadIdx.x;   // 0 .. 262143
    int h  = idx & (H_SZ - 1);
    int bc = idx >> 10;
    int c  = bc & (NC - 1);
    int b  = bc >> 5;
    size_t base = ((size_t)b * T_SZ + (size_t)c * CL) * H_SZ + h;

    float acc = g_hini[idx];
    #pragma unroll 4
    for (int t = 0; t < CL; t++) {
        float a  = g_k [base + (size_t)t * H_SZ];
        float bb = g_th[base + (size_t)t * H_SZ];
        acc = fmaf(a, acc, bb);
        out[base + (size_t)t * H_SZ] = acc;
    }
}

// ---------------------------------------------------------------------------
extern "C" void kernel_launch(void* const* d_in, const int* in_sizes, int n_in,
                              void* d_out, int out_size)
{
    const float* x  = (const float*)d_in[0];
    const float* Wz = (const float*)d_in[1];
    const float* bz = (const float*)d_in[2];
    const float* Wh = (const float*)d_in[3];
    const float* bh = (const float*)d_in[4];
    float* out = (float*)d_out;

    dim3 ggrid(2 * H_SZ / BN, M_TOT / BM);   // (32, 256)
    gemm_kernel<<<ggrid, 256>>>(x, Wz, Wh);

    ew_kernel<<<(M_TOT * H_SZ) / 256, 256>>>(bz, bh);

    scan1_kernel<<<(B_SZ * NC * H_SZ) / 256, 256>>>();
    scan2_kernel<<<(B_SZ * H_SZ) / 256, 256>>>();
    scan3_kernel<<<(B_SZ * NC * H_SZ) / 256, 256>>>(out);
}

// round 3
// speedup vs baseline: 1.9339x; 1.9339x over previous
#include <cuda_runtime.h>
#include <cstdint>

#define B_SZ 8
#define T_SZ 4096
#define D_SZ 1024
#define H_SZ 1024
#define M_TOT (B_SZ * T_SZ)   // 32768
#define NC 32                  // chunks along T (scan)
#define CL 128                 // chunk length (NC*CL = T_SZ)

// Scratch (static __device__ arrays — no allocation in kernel_launch)
__device__ float g_k [M_TOT * H_SZ];   // a = sigmoid(-k)
__device__ float g_th[M_TOT * H_SZ];   // b = sigmoid(k)*g(th)
__device__ float g_A   [B_SZ * NC * H_SZ];
__device__ float g_Bc  [B_SZ * NC * H_SZ];
__device__ float g_hini[B_SZ * NC * H_SZ];

// ===========================================================================
// Helpers
// ===========================================================================
__device__ __forceinline__ uint32_t smem_u32(const void* p) {
    uint32_t a;
    asm("{ .reg .u64 t; cvta.to.shared.u64 t, %1; cvt.u32.u64 %0, t; }" : "=r"(a) : "l"(p));
    return a;
}
__device__ __forceinline__ void cp_async16(uint32_t dst, const void* src) {
    asm volatile("cp.async.cg.shared.global [%0], [%1], 16;\n" :: "r"(dst), "l"(src));
}
#define CP_COMMIT() asm volatile("cp.async.commit_group;\n" ::: "memory")
#define CP_WAIT(N)  asm volatile("cp.async.wait_group %0;\n" :: "n"(N) : "memory")

__device__ __forceinline__ uint32_t f2tf(float f) {
    uint32_t r;
    asm("cvt.rna.tf32.f32 %0, %1;" : "=r"(r) : "f"(f));
    return r;
}
__device__ __forceinline__ void mma_tf32(float& c0, float& c1, float& c2, float& c3,
                                         uint32_t a0, uint32_t a1, uint32_t a2, uint32_t a3,
                                         uint32_t b0, uint32_t b1) {
    asm volatile(
        "mma.sync.aligned.m16n8k8.row.col.f32.tf32.tf32.f32 "
        "{%0,%1,%2,%3}, {%4,%5,%6,%7}, {%8,%9}, {%0,%1,%2,%3};"
        : "+f"(c0), "+f"(c1), "+f"(c2), "+f"(c3)
        : "r"(a0), "r"(a1), "r"(a2), "r"(a3), "r"(b0), "r"(b1));
}

// ===========================================================================
// Fused GEMM (mma.sync tf32) + bias + gate epilogue.
// CTA: 256 threads, tile M=128 x N=256 where N interleaves (Wz,Wh) pairs:
//   global col n: even -> Wz[h0 + n/2], odd -> Wh[h0 + n/2]
// => each mma accumulator pair (c0,c1)/(c2,c3) is (k, tilde_h) for one h.
// Writes a=sigmoid(-k) -> g_k, b=sigmoid(k)*g(th) -> g_th.
// ===========================================================================
#define BM 128
#define BN 256
#define BK 32
#define STAGES 3
#define PITCH 36                       // floats per smem row (conflict-free)
#define A_FLOATS (BM * PITCH)          // 4608
#define B_FLOATS (BN * PITCH)          // 9216
#define STAGE_FLOATS (A_FLOATS + B_FLOATS)
#define SMEM_DYN (STAGES * STAGE_FLOATS * 4)   // 165888 bytes
#define NCHUNK (D_SZ / BK)             // 32

__global__ void __launch_bounds__(256, 1)
gemm_kernel(const float* __restrict__ x,
            const float* __restrict__ Wz,
            const float* __restrict__ Wh,
            const float* __restrict__ bz,
            const float* __restrict__ bh)
{
    extern __shared__ float smem[];
    const uint32_t smem_b = smem_u32(smem);

    const int tid = threadIdx.x;
    const int wid = tid >> 5;
    const int lid = tid & 31;
    const int gr  = lid >> 2;    // 0..7
    const int gc  = lid & 3;     // 0..3
    const int wm  = wid & 1;     // 2 warp rows (64 M each)
    const int wn  = wid >> 1;    // 4 warp cols (64 N each)
    const int m0  = blockIdx.y * BM;
    const int h0  = blockIdx.x * (BN / 2);   // 128 h per CTA

    // ---- async loader for one K-chunk into stage s
    auto load_chunk = [&](int c, int s) {
        const int k0 = c * BK;
        const uint32_t abase = smem_b + (uint32_t)s * STAGE_FLOATS * 4;
        const uint32_t bbase = abase + A_FLOATS * 4;
        // A: 128 rows x 32 floats = 1024 x 16B
        #pragma unroll
        for (int j = 0; j < 4; j++) {
            int idx = tid + j * 256;
            int r = idx >> 3, q = idx & 7;
            cp_async16(abase + r * (PITCH * 4) + q * 16,
                       &x[(size_t)(m0 + r) * D_SZ + k0 + q * 4]);
        }
        // B: 256 rows x 32 floats = 2048 x 16B (interleaved Wz/Wh)
        #pragma unroll
        for (int j = 0; j < 8; j++) {
            int idx = tid + j * 256;
            int n = idx >> 3, q = idx & 7;
            const float* W = (n & 1) ? Wh : Wz;
            cp_async16(bbase + n * (PITCH * 4) + q * 16,
                       &W[(size_t)(h0 + (n >> 1)) * D_SZ + k0 + q * 4]);
        }
    };

    float acc[4][8][4];
    #pragma unroll
    for (int i = 0; i < 4; i++)
        #pragma unroll
        for (int j = 0; j < 8; j++)
            #pragma unroll
            for (int t = 0; t < 4; t++)
                acc[i][j][t] = 0.0f;

    load_chunk(0, 0); CP_COMMIT();
    load_chunk(1, 1); CP_COMMIT();

    for (int i = 0; i < NCHUNK; i++) {
        if (i == NCHUNK - 1) { CP_WAIT(0); } else { CP_WAIT(1); }
        __syncthreads();
        if (i + 2 < NCHUNK) { load_chunk(i + 2, (i + 2) % STAGES); CP_COMMIT(); }

        const int s = i % STAGES;
        const float* As = smem + (size_t)s * STAGE_FLOATS;
        const float* Bs = As + A_FLOATS;

        #pragma unroll
        for (int ks = 0; ks < 4; ks++) {
            const int kc = ks * 8;
            uint32_t af[4][4], bf[8][2];
            #pragma unroll
            for (int mi = 0; mi < 4; mi++) {
                const int r = wm * 64 + mi * 16 + gr;
                af[mi][0] = f2tf(As[(r    ) * PITCH + kc + gc    ]);
                af[mi][1] = f2tf(As[(r + 8) * PITCH + kc + gc    ]);
                af[mi][2] = f2tf(As[(r    ) * PITCH + kc + gc + 4]);
                af[mi][3] = f2tf(As[(r + 8) * PITCH + kc + gc + 4]);
            }
            #pragma unroll
            for (int nj = 0; nj < 8; nj++) {
                const int n = wn * 64 + nj * 8 + gr;
                bf[nj][0] = f2tf(Bs[n * PITCH + kc + gc    ]);
                bf[nj][1] = f2tf(Bs[n * PITCH + kc + gc + 4]);
            }
            #pragma unroll
            for (int mi = 0; mi < 4; mi++)
                #pragma unroll
                for (int nj = 0; nj < 8; nj++)
                    mma_tf32(acc[mi][nj][0], acc[mi][nj][1],
                             acc[mi][nj][2], acc[mi][nj][3],
                             af[mi][0], af[mi][1], af[mi][2], af[mi][3],
                             bf[nj][0], bf[nj][1]);
        }
        __syncthreads();
    }

    // ---- epilogue: gates in registers, scalar stores
    #pragma unroll
    for (int mi = 0; mi < 4; mi++) {
        #pragma unroll
        for (int nj = 0; nj < 8; nj++) {
            const int h = h0 + wn * 32 + nj * 4 + gc;
            const float bzv = __ldg(&bz[h]);
            const float bhv = __ldg(&bh[h]);
            #pragma unroll
            for (int half = 0; half < 2; half++) {
                const int m = m0 + wm * 64 + mi * 16 + gr + half * 8;
                float k  = acc[mi][nj][half * 2 + 0] + bzv;
                float th = acc[mi][nj][half * 2 + 1] + bhv;
                float em  = __expf(-fabsf(k));
                float inv = 1.0f / (1.0f + em);
                float z, a;
                if (k >= 0.0f) { z = inv;      a = em * inv; }
                else           { z = em * inv; a = inv;      }
                float g;
                if (th >= 0.0f) g = th + 0.5f;
                else            g = 1.0f / (1.0f + __expf(-th));
                g_k [(size_t)m * H_SZ + h] = a;
                g_th[(size_t)m * H_SZ + h] = z * g;
            }
        }
    }
}

// ===========================================================================
// Chunked scan: h[t] = a[t]*h[t-1] + b[t], h[-1] = 0
// ===========================================================================
__global__ __launch_bounds__(256) void scan1_kernel()
{
    int idx = blockIdx.x * 256 + threadIdx.x;   // 0 .. B*NC*H-1
    int h  = idx & (H_SZ - 1);
    int bc = idx >> 10;
    int c  = bc & (NC - 1);
    int b  = bc >> 5;
    size_t base = ((size_t)b * T_SZ + (size_t)c * CL) * H_SZ + h;

    float A = 1.0f, acc = 0.0f;
    #pragma unroll 4
    for (int t = 0; t < CL; t++) {
        float a  = g_k [base + (size_t)t * H_SZ];
        float bb = g_th[base + (size_t)t * H_SZ];
        A *= a;
        acc = fmaf(a, acc, bb);
    }
    g_A [idx] = A;
    g_Bc[idx] = acc;
}

__global__ __launch_bounds__(256) void scan2_kernel()
{
    int idx = blockIdx.x * 256 + threadIdx.x;   // 0 .. B*H-1
    int h = idx & (H_SZ - 1);
    int b = idx >> 10;
    float carry = 0.0f;
    #pragma unroll
    for (int c = 0; c < NC; c++) {
        int j = (b * NC + c) * H_SZ + h;
        g_hini[j] = carry;
        carry = fmaf(g_A[j], carry, g_Bc[j]);
    }
}

__global__ __launch_bounds__(256) void scan3_kernel(float* __restrict__ out)
{
    int idx = blockIdx.x * 256 + threadIdx.x;
    int h  = idx & (H_SZ - 1);
    int bc = idx >> 10;
    int c  = bc & (NC - 1);
    int b  = bc >> 5;
    size_t base = ((size_t)b * T_SZ + (size_t)c * CL) * H_SZ + h;

    float acc = g_hini[idx];
    #pragma unroll 4
    for (int t = 0; t < CL; t++) {
        float a  = g_k [base + (size_t)t * H_SZ];
        float bb = g_th[base + (size_t)t * H_SZ];
        acc = fmaf(a, acc, bb);
        out[base + (size_t)t * H_SZ] = acc;
    }
}

// ===========================================================================
extern "C" void kernel_launch(void* const* d_in, const int* in_sizes, int n_in,
                              void* d_out, int out_size)
{
    const float* x  = (const float*)d_in[0];
    const float* Wz = (const float*)d_in[1];
    const float* bz = (const float*)d_in[2];
    const float* Wh = (const float*)d_in[3];
    const float* bh = (const float*)d_in[4];
    float* out = (float*)d_out;

    cudaFuncSetAttribute(gemm_kernel,
                         cudaFuncAttributeMaxDynamicSharedMemorySize, SMEM_DYN);

    dim3 ggrid(H_SZ / (BN / 2), M_TOT / BM);   // (8, 256)
    gemm_kernel<<<ggrid, 256, SMEM_DYN>>>(x, Wz, Wh, bz, bh);

    scan1_kernel<<<(B_SZ * NC * H_SZ) / 256, 256>>>();
    scan2_kernel<<<(B_SZ * H_SZ) / 256, 256>>>();
    scan3_kernel<<<(B_SZ * NC * H_SZ) / 256, 256>>>(out);
}

// round 4
// speedup vs baseline: 2.0614x; 1.0660x over previous
#include <cuda_runtime.h>
#include <cstdint>

#define B_SZ 8
#define T_SZ 4096
#define D_SZ 1024
#define H_SZ 1024
#define M_TOT (B_SZ * T_SZ)   // 32768
#define NC 32                  // chunks along T (scan)
#define CL 128                 // chunk length (NC*CL = T_SZ)

// Scratch (static __device__ arrays — no allocation in kernel_launch)
__device__ float g_k [M_TOT * H_SZ];   // a = sigmoid(-k)
__device__ float g_th[M_TOT * H_SZ];   // b = sigmoid(k)*g(th)
__device__ float g_A   [B_SZ * NC * H_SZ];
__device__ float g_Bc  [B_SZ * NC * H_SZ];
__device__ float g_hini[B_SZ * NC * H_SZ];

// ===========================================================================
// Helpers
// ===========================================================================
__device__ __forceinline__ uint32_t smem_u32(const void* p) {
    uint32_t a;
    asm("{ .reg .u64 t; cvta.to.shared.u64 t, %1; cvt.u32.u64 %0, t; }" : "=r"(a) : "l"(p));
    return a;
}
__device__ __forceinline__ void cp_async16(uint32_t dst, const void* src) {
    asm volatile("cp.async.cg.shared.global [%0], [%1], 16;\n" :: "r"(dst), "l"(src));
}
#define CP_COMMIT() asm volatile("cp.async.commit_group;\n" ::: "memory")
#define CP_WAIT(N)  asm volatile("cp.async.wait_group %0;\n" :: "n"(N) : "memory")

__device__ __forceinline__ void mma_tf32(float& c0, float& c1, float& c2, float& c3,
                                         uint32_t a0, uint32_t a1, uint32_t a2, uint32_t a3,
                                         uint32_t b0, uint32_t b1) {
    asm volatile(
        "mma.sync.aligned.m16n8k8.row.col.f32.tf32.tf32.f32 "
        "{%0,%1,%2,%3}, {%4,%5,%6,%7}, {%8,%9}, {%0,%1,%2,%3};"
        : "+f"(c0), "+f"(c1), "+f"(c2), "+f"(c3)
        : "r"(a0), "r"(a1), "r"(a2), "r"(a3), "r"(b0), "r"(b1));
}

// ===========================================================================
// Fused GEMM (mma.sync tf32, raw-fp32-bit operands = HW truncation) + gates.
// CTA: 256 threads, tile M=128 x N=256; N interleaves (Wz,Wh) pairs:
//   col n even -> Wz[h0 + n/2] (k), odd -> Wh[h0 + n/2] (tilde_h)
// Each accumulator pair (c0,c1)/(c2,c3) = (k, tilde_h) for one h.
// BK=64, 2-stage cp.async double buffer, register-double-buffered fragments.
// ===========================================================================
#define BM 128
#define BN 256
#define BK 64
#define PITCH 68                       // floats per smem row (4*gr+gc+c covers banks)
#define A_FLOATS (BM * PITCH)          // 8704
#define B_FLOATS (BN * PITCH)          // 17408
#define STAGE_FLOATS (A_FLOATS + B_FLOATS)          // 26112
#define SMEM_DYN (2 * STAGE_FLOATS * 4)             // 208896 bytes
#define NCHUNK (D_SZ / BK)             // 16

__global__ void __launch_bounds__(256, 1)
gemm_kernel(const float* __restrict__ x,
            const float* __restrict__ Wz,
            const float* __restrict__ Wh,
            const float* __restrict__ bz,
            const float* __restrict__ bh)
{
    extern __shared__ float smem[];
    const uint32_t smem_b = smem_u32(smem);

    const int tid = threadIdx.x;
    const int wid = tid >> 5;
    const int lid = tid & 31;
    const int gr  = lid >> 2;    // 0..7
    const int gc  = lid & 3;     // 0..3
    const int wm  = wid & 1;     // 2 warp rows (64 M each)
    const int wn  = wid >> 1;    // 4 warp cols (64 N each)
    const int m0  = blockIdx.y * BM;
    const int h0  = blockIdx.x * (BN / 2);   // 128 h per CTA

    // ---- async loader for one K-chunk into stage s
    auto load_chunk = [&](int c, int s) {
        const int k0 = c * BK;
        const uint32_t abase = smem_b + (uint32_t)s * STAGE_FLOATS * 4;
        const uint32_t bbase = abase + A_FLOATS * 4;
        // A: 128 rows x 64 floats = 2048 x 16B -> 8 per thread
        #pragma unroll
        for (int j = 0; j < 8; j++) {
            int idx = tid + j * 256;
            int r = idx >> 4, q = idx & 15;
            cp_async16(abase + r * (PITCH * 4) + q * 16,
                       &x[(size_t)(m0 + r) * D_SZ + k0 + q * 4]);
        }
        // B: 256 rows x 64 floats = 4096 x 16B -> 16 per thread (interleaved Wz/Wh)
        #pragma unroll
        for (int j = 0; j < 16; j++) {
            int idx = tid + j * 256;
            int n = idx >> 4, q = idx & 15;
            const float* W = (n & 1) ? Wh : Wz;
            cp_async16(bbase + n * (PITCH * 4) + q * 16,
                       &W[(size_t)(h0 + (n >> 1)) * D_SZ + k0 + q * 4]);
        }
    };

    float acc[4][8][4];
    #pragma unroll
    for (int i = 0; i < 4; i++)
        #pragma unroll
        for (int j = 0; j < 8; j++)
            #pragma unroll
            for (int t = 0; t < 4; t++)
                acc[i][j][t] = 0.0f;

    load_chunk(0, 0); CP_COMMIT();

    for (int i = 0; i < NCHUNK; i++) {
        const int s = i & 1;
        // prefetch next chunk into other stage (consumed-last two iters ago;
        // the trailing __syncthreads of iter i-1 guards the overwrite)
        if (i + 1 < NCHUNK) { load_chunk(i + 1, s ^ 1); CP_COMMIT(); CP_WAIT(1); }
        else                { CP_WAIT(0); }
        __syncthreads();   // chunk i visible to all warps

        const float* As = smem + (size_t)s * STAGE_FLOATS;
        const float* Bs = As + A_FLOATS;

        // fragment register double buffer
        uint32_t af[2][4][4], bf[2][8][2];

        auto load_frags = [&](int ks, int rb) {
            const int kc = ks * 8;
            #pragma unroll
            for (int mi = 0; mi < 4; mi++) {
                const int r = wm * 64 + mi * 16 + gr;
                af[rb][mi][0] = __float_as_uint(As[(r    ) * PITCH + kc + gc    ]);
                af[rb][mi][1] = __float_as_uint(As[(r + 8) * PITCH + kc + gc    ]);
                af[rb][mi][2] = __float_as_uint(As[(r    ) * PITCH + kc + gc + 4]);
                af[rb][mi][3] = __float_as_uint(As[(r + 8) * PITCH + kc + gc + 4]);
            }
            #pragma unroll
            for (int nj = 0; nj < 8; nj++) {
                const int n = wn * 64 + nj * 8 + gr;
                bf[rb][nj][0] = __float_as_uint(Bs[n * PITCH + kc + gc    ]);
                bf[rb][nj][1] = __float_as_uint(Bs[n * PITCH + kc + gc + 4]);
            }
        };

        load_frags(0, 0);
        #pragma unroll
        for (int ks = 0; ks < 8; ks++) {
            const int cur = ks & 1;
            if (ks + 1 < 8) load_frags(ks + 1, cur ^ 1);
            #pragma unroll
            for (int mi = 0; mi < 4; mi++)
                #pragma unroll
                for (int nj = 0; nj < 8; nj++)
                    mma_tf32(acc[mi][nj][0], acc[mi][nj][1],
                             acc[mi][nj][2], acc[mi][nj][3],
                             af[cur][mi][0], af[cur][mi][1],
                             af[cur][mi][2], af[cur][mi][3],
                             bf[cur][nj][0], bf[cur][nj][1]);
        }
        __syncthreads();   // all warps done with stage s before it is refilled
    }

    // ---- epilogue: gates in registers, scalar stores
    #pragma unroll
    for (int mi = 0; mi < 4; mi++) {
        #pragma unroll
        for (int nj = 0; nj < 8; nj++) {
            const int h = h0 + wn * 32 + nj * 4 + gc;
            const float bzv = __ldg(&bz[h]);
            const float bhv = __ldg(&bh[h]);
            #pragma unroll
            for (int half = 0; half < 2; half++) {
                const int m = m0 + wm * 64 + mi * 16 + gr + half * 8;
                float k  = acc[mi][nj][half * 2 + 0] + bzv;
                float th = acc[mi][nj][half * 2 + 1] + bhv;
                float em  = __expf(-fabsf(k));
                float inv = 1.0f / (1.0f + em);
                float z, a;
                if (k >= 0.0f) { z = inv;      a = em * inv; }
                else           { z = em * inv; a = inv;      }
                float g;
                if (th >= 0.0f) g = th + 0.5f;
                else            g = 1.0f / (1.0f + __expf(-th));
                g_k [(size_t)m * H_SZ + h] = a;
                g_th[(size_t)m * H_SZ + h] = z * g;
            }
        }
    }
}

// ===========================================================================
// Chunked scan: h[t] = a[t]*h[t-1] + b[t], h[-1] = 0
// ===========================================================================
__global__ __launch_bounds__(256) void scan1_kernel()
{
    int idx = blockIdx.x * 256 + threadIdx.x;   // 0 .. B*NC*H-1
    int h  = idx & (H_SZ - 1);
    int bc = idx >> 10;
    int c  = bc & (NC - 1);
    int b  = bc >> 5;
    size_t base = ((size_t)b * T_SZ + (size_t)c * CL) * H_SZ + h;

    float A = 1.0f, acc = 0.0f;
    #pragma unroll 4
    for (int t = 0; t < CL; t++) {
        float a  = g_k [base + (size_t)t * H_SZ];
        float bb = g_th[base + (size_t)t * H_SZ];
        A *= a;
        acc = fmaf(a, acc, bb);
    }
    g_A [idx] = A;
    g_Bc[idx] = acc;
}

__global__ __launch_bounds__(256) void scan2_kernel()
{
    int idx = blockIdx.x * 256 + threadIdx.x;   // 0 .. B*H-1
    int h = idx & (H_SZ - 1);
    int b = idx >> 10;
    float carry = 0.0f;
    #pragma unroll
    for (int c = 0; c < NC; c++) {
        int j = (b * NC + c) * H_SZ + h;
        g_hini[j] = carry;
        carry = fmaf(g_A[j], carry, g_Bc[j]);
    }
}

__global__ __launch_bounds__(256) void scan3_kernel(float* __restrict__ out)
{
    int idx = blockIdx.x * 256 + threadIdx.x;
    int h  = idx & (H_SZ - 1);
    int bc = idx >> 10;
    int c  = bc & (NC - 1);
    int b  = bc >> 5;
    size_t base = ((size_t)b * T_SZ + (size_t)c * CL) * H_SZ + h;

    float acc = g_hini[idx];
    #pragma unroll 4
    for (int t = 0; t < CL; t++) {
        float a  = g_k [base + (size_t)t * H_SZ];
        float bb = g_th[base + (size_t)t * H_SZ];
        acc = fmaf(a, acc, bb);
        out[base + (size_t)t * H_SZ] = acc;
    }
}

// ===========================================================================
extern "C" void kernel_launch(void* const* d_in, const int* in_sizes, int n_in,
                              void* d_out, int out_size)
{
    const float* x  = (const float*)d_in[0];
    const float* Wz = (const float*)d_in[1];
    const float* bz = (const float*)d_in[2];
    const float* Wh = (const float*)d_in[3];
    const float* bh = (const float*)d_in[4];
    float* out = (float*)d_out;

    cudaFuncSetAttribute(gemm_kernel,
                         cudaFuncAttributeMaxDynamicSharedMemorySize, SMEM_DYN);

    dim3 ggrid(H_SZ / (BN / 2), M_TOT / BM);   // (8, 256)
    gemm_kernel<<<ggrid, 256, SMEM_DYN>>>(x, Wz, Wh, bz, bh);

    scan1_kernel<<<(B_SZ * NC * H_SZ) / 256, 256>>>();
    scan2_kernel<<<(B_SZ * H_SZ) / 256, 256>>>();
    scan3_kernel<<<(B_SZ * NC * H_SZ) / 256, 256>>>(out);
}

// round 6
// speedup vs baseline: 2.1571x; 1.0464x over previous
#include <cuda_runtime.h>
#include <cuda_fp16.h>
#include <cstdint>

#define B_SZ 8
#define T_SZ 4096
#define D_SZ 1024
#define H_SZ 1024
#define M_TOT (B_SZ * T_SZ)   // 32768
#define NC 32                  // chunks along T (scan)
#define CL 128                 // chunk length (NC*CL = T_SZ)

// Scratch (static __device__ arrays — no allocation in kernel_launch)
__device__ float g_k [M_TOT * H_SZ];   // a = sigmoid(-k)
__device__ float g_th[M_TOT * H_SZ];   // b = sigmoid(k)*g(th)
__device__ float g_A   [B_SZ * NC * H_SZ];
__device__ float g_Bc  [B_SZ * NC * H_SZ];
__device__ float g_hini[B_SZ * NC * H_SZ];
__device__ __half g_xh [M_TOT * D_SZ];  // fp16 copies for tensor path
__device__ __half g_wzh[H_SZ * D_SZ];
__device__ __half g_whh[H_SZ * D_SZ];

// ===========================================================================
// Helpers
// ===========================================================================
__device__ __forceinline__ uint32_t smem_u32(const void* p) {
    uint32_t a;
    asm("{ .reg .u64 t; cvta.to.shared.u64 t, %1; cvt.u32.u64 %0, t; }" : "=r"(a) : "l"(p));
    return a;
}
__device__ __forceinline__ void cp_async16(uint32_t dst, const void* src) {
    asm volatile("cp.async.cg.shared.global [%0], [%1], 16;\n" :: "r"(dst), "l"(src));
}
#define CP_COMMIT() asm volatile("cp.async.commit_group;\n" ::: "memory")
#define CP_WAIT(N)  asm volatile("cp.async.wait_group %0;\n" :: "n"(N) : "memory")

__device__ __forceinline__ void mma_f16(float& c0, float& c1, float& c2, float& c3,
                                        uint32_t a0, uint32_t a1, uint32_t a2, uint32_t a3,
                                        uint32_t b0, uint32_t b1) {
    asm volatile(
        "mma.sync.aligned.m16n8k16.row.col.f32.f16.f16.f32 "
        "{%0,%1,%2,%3}, {%4,%5,%6,%7}, {%8,%9}, {%0,%1,%2,%3};"
        : "+f"(c0), "+f"(c1), "+f"(c2), "+f"(c3)
        : "r"(a0), "r"(a1), "r"(a2), "r"(a3), "r"(b0), "r"(b1));
}

// ===========================================================================
// fp32 -> fp16 conversion pass (8 elems/thread, vectorized)
// ===========================================================================
__global__ __launch_bounds__(256) void cvt_kernel(const float* __restrict__ src,
                                                  __half* __restrict__ dst)
{
    size_t i = ((size_t)blockIdx.x * 256 + threadIdx.x) * 8;
    float4 v0 = *reinterpret_cast<const float4*>(src + i);
    float4 v1 = *reinterpret_cast<const float4*>(src + i + 4);
    __half2 h[4];
    h[0] = __floats2half2_rn(v0.x, v0.y);
    h[1] = __floats2half2_rn(v0.z, v0.w);
    h[2] = __floats2half2_rn(v1.x, v1.y);
    h[3] = __floats2half2_rn(v1.z, v1.w);
    *reinterpret_cast<uint4*>(dst + i) = *reinterpret_cast<uint4*>(h);
}

// ===========================================================================
// Fused GEMM (mma.sync fp16, fp32 accum) + bias + gate epilogue.
// CTA: 256 threads, tile M=128 x N=256; N interleaves (Wz,Wh) pairs:
//   col n even -> Wz[h0 + n/2] (k), odd -> Wh[h0 + n/2] (tilde_h)
// Accumulator pair (c0,c1)/(c2,c3) = (k, tilde_h) for one h.
// BK=64 halfs, 3-stage cp.async pipeline.
// ===========================================================================
#define BM 128
#define BN 256
#define BK 64                           // halfs per chunk = 4 x k16 steps
#define STAGES 3
#define PITCHW 36                       // 32-bit words per smem row (128B data + 16B pad)
#define A_WORDS (BM * PITCHW)           // 4608
#define B_WORDS (BN * PITCHW)           // 9216
#define STAGE_WORDS (A_WORDS + B_WORDS) // 13824
#define SMEM_DYN (STAGES * STAGE_WORDS * 4)   // 165888 bytes
#define NCHUNK (D_SZ / BK)              // 16

__global__ void __launch_bounds__(256, 1)
gemm_kernel(const float* __restrict__ bz,
            const float* __restrict__ bh)
{
    extern __shared__ uint32_t smem[];
    const uint32_t smem_b = smem_u32(smem);

    const int tid = threadIdx.x;
    const int wid = tid >> 5;
    const int lid = tid & 31;
    const int gr  = lid >> 2;    // 0..7
    const int gc  = lid & 3;     // 0..3
    const int wm  = wid & 1;     // 2 warp rows (64 M each)
    const int wn  = wid >> 1;    // 4 warp cols (64 N each)
    const int m0  = blockIdx.y * BM;
    const int h0  = blockIdx.x * (BN / 2);   // 128 h per CTA

    // ---- async loader: one K-chunk (64 halfs = 128B/row) into stage s
    auto load_chunk = [&](int c, int s) {
        const int k0 = c * BK;
        const uint32_t abase = smem_b + (uint32_t)s * STAGE_WORDS * 4;
        const uint32_t bbase = abase + A_WORDS * 4;
        // A: 128 rows x 8 chunks of 16B -> 1024 cp.async, 4/thread
        #pragma unroll
        for (int j = 0; j < 4; j++) {
            int idx = tid + j * 256;
            int r = idx >> 3, q = idx & 7;
            cp_async16(abase + r * (PITCHW * 4) + q * 16,
                       &g_xh[(size_t)(m0 + r) * D_SZ + k0 + q * 8]);
        }
        // B: 256 rows x 8 chunks -> 2048 cp.async, 8/thread (interleaved Wz/Wh)
        #pragma unroll
        for (int j = 0; j < 8; j++) {
            int idx = tid + j * 256;
            int n = idx >> 3, q = idx & 7;
            const __half* W = (n & 1) ? g_whh : g_wzh;
            cp_async16(bbase + n * (PITCHW * 4) + q * 16,
                       &W[(size_t)(h0 + (n >> 1)) * D_SZ + k0 + q * 8]);
        }
    };

    float acc[4][8][4];
    #pragma unroll
    for (int i = 0; i < 4; i++)
        #pragma unroll
        for (int j = 0; j < 8; j++)
            #pragma unroll
            for (int t = 0; t < 4; t++)
                acc[i][j][t] = 0.0f;

    load_chunk(0, 0); CP_COMMIT();
    load_chunk(1, 1); CP_COMMIT();

    for (int i = 0; i < NCHUNK; i++) {
        if (i == NCHUNK - 1) { CP_WAIT(0); } else { CP_WAIT(1); }
        __syncthreads();
        if (i + 2 < NCHUNK) { load_chunk(i + 2, (i + 2) % STAGES); CP_COMMIT(); }

        const int s = i % STAGES;
        const uint32_t* As = smem + (size_t)s * STAGE_WORDS;
        const uint32_t* Bs = As + A_WORDS;

        // 4 k16 steps; word index within row = ks*8 + gc (+4 for k+8 halfs)
        #pragma unroll
        for (int ks = 0; ks < 4; ks++) {
            const int kw = ks * 8;
            uint32_t af[4][4], bf[8][2];
            #pragma unroll
            for (int mi = 0; mi < 4; mi++) {
                const int r = wm * 64 + mi * 16 + gr;
                af[mi][0] = As[(r    ) * PITCHW + kw + gc    ];
                af[mi][1] = As[(r + 8) * PITCHW + kw + gc    ];
                af[mi][2] = As[(r    ) * PITCHW + kw + gc + 4];
                af[mi][3] = As[(r + 8) * PITCHW + kw + gc + 4];
            }
            #pragma unroll
            for (int nj = 0; nj < 8; nj++) {
                const int n = wn * 64 + nj * 8 + gr;
                bf[nj][0] = Bs[n * PITCHW + kw + gc    ];
                bf[nj][1] = Bs[n * PITCHW + kw + gc + 4];
            }
            #pragma unroll
            for (int mi = 0; mi < 4; mi++)
                #pragma unroll
                for (int nj = 0; nj < 8; nj++)
                    mma_f16(acc[mi][nj][0], acc[mi][nj][1],
                            acc[mi][nj][2], acc[mi][nj][3],
                            af[mi][0], af[mi][1], af[mi][2], af[mi][3],
                            bf[nj][0], bf[nj][1]);
        }
        __syncthreads();
    }

    // ---- epilogue: gates in registers, scalar stores
    #pragma unroll
    for (int mi = 0; mi < 4; mi++) {
        #pragma unroll
        for (int nj = 0; nj < 8; nj++) {
            const int h = h0 + wn * 32 + nj * 4 + gc;
            const float bzv = __ldg(&bz[h]);
            const float bhv = __ldg(&bh[h]);
            #pragma unroll
            for (int half = 0; half < 2; half++) {
                const int m = m0 + wm * 64 + mi * 16 + gr + half * 8;
                float k  = acc[mi][nj][half * 2 + 0] + bzv;
                float th = acc[mi][nj][half * 2 + 1] + bhv;
                float em  = __expf(-fabsf(k));
                float inv = 1.0f / (1.0f + em);
                float z, a;
                if (k >= 0.0f) { z = inv;      a = em * inv; }
                else           { z = em * inv; a = inv;      }
                float g;
                if (th >= 0.0f) g = th + 0.5f;
                else            g = 1.0f / (1.0f + __expf(-th));
                g_k [(size_t)m * H_SZ + h] = a;
                g_th[(size_t)m * H_SZ + h] = z * g;
            }
        }
    }
}

// ===========================================================================
// Chunked scan: h[t] = a[t]*h[t-1] + b[t], h[-1] = 0
// ===========================================================================
__global__ __launch_bounds__(256) void scan1_kernel()
{
    int idx = blockIdx.x * 256 + threadIdx.x;   // 0 .. B*NC*H-1
    int h  = idx & (H_SZ - 1);
    int bc = idx >> 10;
    int c  = bc & (NC - 1);
    int b  = bc >> 5;
    size_t base = ((size_t)b * T_SZ + (size_t)c * CL) * H_SZ + h;

    float A = 1.0f, acc = 0.0f;
    #pragma unroll 4
    for (int t = 0; t < CL; t++) {
        float a  = g_k [base + (size_t)t * H_SZ];
        float bb = g_th[base + (size_t)t * H_SZ];
        A *= a;
        acc = fmaf(a, acc, bb);
    }
    g_A [idx] = A;
    g_Bc[idx] = acc;
}

__global__ __launch_bounds__(256) void scan2_kernel()
{
    int idx = blockIdx.x * 256 + threadIdx.x;   // 0 .. B*H-1
    int h = idx & (H_SZ - 1);
    int b = idx >> 10;
    float carry = 0.0f;
    #pragma unroll
    for (int c = 0; c < NC; c++) {
        int j = (b * NC + c) * H_SZ + h;
        g_hini[j] = carry;
        carry = fmaf(g_A[j], carry, g_Bc[j]);
    }
}

__global__ __launch_bounds__(256) void scan3_kernel(float* __restrict__ out)
{
    int idx = blockIdx.x * 256 + threadIdx.x;
    int h  = idx & (H_SZ - 1);
    int bc = idx >> 10;
    int c  = bc & (NC - 1);
    int b  = bc >> 5;
    size_t base = ((size_t)b * T_SZ + (size_t)c * CL) * H_SZ + h;

    float acc = g_hini[idx];
    #pragma unroll 4
    for (int t = 0; t < CL; t++) {
        float a  = g_k [base + (size_t)t * H_SZ];
        float bb = g_th[base + (size_t)t * H_SZ];
        acc = fmaf(a, acc, bb);
        out[base + (size_t)t * H_SZ] = acc;
    }
}

// ===========================================================================
extern "C" void kernel_launch(void* const* d_in, const int* in_sizes, int n_in,
                              void* d_out, int out_size)
{
    const float* x  = (const float*)d_in[0];
    const float* Wz = (const float*)d_in[1];
    const float* bz = (const float*)d_in[2];
    const float* Wh = (const float*)d_in[3];
    const float* bh = (const float*)d_in[4];
    float* out = (float*)d_out;

    cudaFuncSetAttribute(gemm_kernel,
                         cudaFuncAttributeMaxDynamicSharedMemorySize, SMEM_DYN);

    // fp32 -> fp16 conversion
    __half* xh;  cudaGetSymbolAddress((void**)&xh,  g_xh);
    __half* wzh; cudaGetSymbolAddress((void**)&wzh, g_wzh);
    __half* whh; cudaGetSymbolAddress((void**)&whh, g_whh);
    cvt_kernel<<<(M_TOT * D_SZ) / (256 * 8), 256>>>(x,  xh);
    cvt_kernel<<<(H_SZ * D_SZ) / (256 * 8), 256>>>(Wz, wzh);
    cvt_kernel<<<(H_SZ * D_SZ) / (256 * 8), 256>>>(Wh, whh);

    dim3 ggrid(H_SZ / (BN / 2), M_TOT / BM);   // (8, 256)
    gemm_kernel<<<ggrid, 256, SMEM_DYN>>>(bz, bh);

    scan1_kernel<<<(B_SZ * NC * H_SZ) / 256, 256>>>();
    scan2_kernel<<<(B_SZ * H_SZ) / 256, 256>>>();
    scan3_kernel<<<(B_SZ * NC * H_SZ) / 256, 256>>>(out);
}

// round 7
// speedup vs baseline: 3.4771x; 1.6120x over previous
#include <cuda_runtime.h>
#include <cuda_fp16.h>
#include <cstdint>

#define B_SZ 8
#define T_SZ 4096
#define D_SZ 1024
#define H_SZ 1024
#define M_TOT (B_SZ * T_SZ)   // 32768
#define NC 32                  // chunks along T (scan)
#define CL 128                 // chunk length (NC*CL = T_SZ)

// Scratch (static __device__ arrays — no allocation in kernel_launch)
__device__ float g_k [M_TOT * H_SZ];   // a = sigmoid(-k)
__device__ float g_th[M_TOT * H_SZ];   // b = sigmoid(k)*g(th)
__device__ float g_A   [B_SZ * NC * H_SZ];
__device__ float g_Bc  [B_SZ * NC * H_SZ];
__device__ float g_hini[B_SZ * NC * H_SZ];
__device__ __half g_xh [M_TOT * D_SZ];  // fp16 copies for tensor path
__device__ __half g_wzh[H_SZ * D_SZ];
__device__ __half g_whh[H_SZ * D_SZ];

// ===========================================================================
// Helpers
// ===========================================================================
__device__ __forceinline__ uint32_t smem_u32(const void* p) {
    uint32_t a;
    asm("{ .reg .u64 t; cvta.to.shared.u64 t, %1; cvt.u32.u64 %0, t; }" : "=r"(a) : "l"(p));
    return a;
}
__device__ __forceinline__ void cp_async16(uint32_t dst, const void* src) {
    asm volatile("cp.async.cg.shared.global [%0], [%1], 16;\n" :: "r"(dst), "l"(src));
}
#define CP_COMMIT() asm volatile("cp.async.commit_group;\n" ::: "memory")
#define CP_WAIT(N)  asm volatile("cp.async.wait_group %0;\n" :: "n"(N) : "memory")

__device__ __forceinline__ void ldsm_x4(uint32_t& r0, uint32_t& r1,
                                        uint32_t& r2, uint32_t& r3, uint32_t addr) {
    asm volatile("ldmatrix.sync.aligned.m8n8.x4.shared.b16 {%0,%1,%2,%3}, [%4];"
                 : "=r"(r0), "=r"(r1), "=r"(r2), "=r"(r3) : "r"(addr));
}

__device__ __forceinline__ void mma_f16(float& c0, float& c1, float& c2, float& c3,
                                        uint32_t a0, uint32_t a1, uint32_t a2, uint32_t a3,
                                        uint32_t b0, uint32_t b1) {
    asm volatile(
        "mma.sync.aligned.m16n8k16.row.col.f32.f16.f16.f32 "
        "{%0,%1,%2,%3}, {%4,%5,%6,%7}, {%8,%9}, {%0,%1,%2,%3};"
        : "+f"(c0), "+f"(c1), "+f"(c2), "+f"(c3)
        : "r"(a0), "r"(a1), "r"(a2), "r"(a3), "r"(b0), "r"(b1));
}

// ===========================================================================
// fp32 -> fp16 conversion pass (8 elems/thread, vectorized)
// ===========================================================================
__global__ __launch_bounds__(256) void cvt_kernel(const float* __restrict__ src,
                                                  __half* __restrict__ dst)
{
    size_t i = ((size_t)blockIdx.x * 256 + threadIdx.x) * 8;
    float4 v0 = *reinterpret_cast<const float4*>(src + i);
    float4 v1 = *reinterpret_cast<const float4*>(src + i + 4);
    __half2 h[4];
    h[0] = __floats2half2_rn(v0.x, v0.y);
    h[1] = __floats2half2_rn(v0.z, v0.w);
    h[2] = __floats2half2_rn(v1.x, v1.y);
    h[3] = __floats2half2_rn(v1.z, v1.w);
    *reinterpret_cast<uint4*>(dst + i) = *reinterpret_cast<uint4*>(h);
}

// ===========================================================================
// Fused GEMM (mma.sync fp16, fp32 accum, ldmatrix) + bias + gate epilogue.
// 512 threads = 16 warps: 2 warp-rows (64 M) x 8 warp-cols (32 N).
// Tile M=128 x N=256; N interleaves (Wz,Wh): col even -> k, odd -> tilde_h.
// ===========================================================================
#define BM 128
#define BN 256
#define BK 64                           // halfs per chunk = 4 x k16 steps
#define STAGES 3
#define PITCHW 36                       // 32-bit words per smem row
#define PITCHB (PITCHW * 4)             // 144 bytes
#define A_WORDS (BM * PITCHW)           // 4608
#define B_WORDS (BN * PITCHW)           // 9216
#define STAGE_WORDS (A_WORDS + B_WORDS) // 13824
#define SMEM_DYN (STAGES * STAGE_WORDS * 4)   // 165888 bytes
#define NCHUNK (D_SZ / BK)              // 16

__global__ void __launch_bounds__(512, 1)
gemm_kernel(const float* __restrict__ bz,
            const float* __restrict__ bh)
{
    extern __shared__ uint32_t smem[];
    const uint32_t smem_b = smem_u32(smem);

    const int tid = threadIdx.x;
    const int wid = tid >> 5;
    const int lid = tid & 31;
    const int gr  = lid >> 2;    // 0..7
    const int gc  = lid & 3;     // 0..3
    const int wm  = wid & 1;     // 2 warp rows (64 M each)
    const int wn  = wid >> 1;    // 8 warp cols (32 N each)
    const int m0  = blockIdx.y * BM;
    const int h0  = blockIdx.x * (BN / 2);   // 128 h per CTA

    // ---- per-lane ldmatrix byte offsets (within a stage)
    // A x4: mat l/8: row = lid&15, khalf = lid>>4 (16B)
    const uint32_t aLane = (uint32_t)(wm * 64 + (lid & 15)) * PITCHB + (uint32_t)(lid >> 4) * 16;
    // B x4 (nj pair p): row n = wn*32 + p*16 + ((lid>>4)&1)*8 + (lid&7); koff=((lid>>3)&1)*16
    const uint32_t bLane = A_WORDS * 4
        + (uint32_t)(wn * 32 + ((lid >> 4) & 1) * 8 + (lid & 7)) * PITCHB
        + (uint32_t)((lid >> 3) & 1) * 16;

    // ---- async loader: one K-chunk (64 halfs = 128B/row) into stage s
    auto load_chunk = [&](int c, int s) {
        const int k0 = c * BK;
        const uint32_t abase = smem_b + (uint32_t)s * STAGE_WORDS * 4;
        const uint32_t bbase = abase + A_WORDS * 4;
        // A: 128 rows x 8 x 16B = 1024 -> 2/thread
        #pragma unroll
        for (int j = 0; j < 2; j++) {
            int idx = tid + j * 512;
            int r = idx >> 3, q = idx & 7;
            cp_async16(abase + r * PITCHB + q * 16,
                       &g_xh[(size_t)(m0 + r) * D_SZ + k0 + q * 8]);
        }
        // B: 256 rows x 8 x 16B = 2048 -> 4/thread (interleaved Wz/Wh)
        #pragma unroll
        for (int j = 0; j < 4; j++) {
            int idx = tid + j * 512;
            int n = idx >> 3, q = idx & 7;
            const __half* W = (n & 1) ? g_whh : g_wzh;
            cp_async16(bbase + n * PITCHB + q * 16,
                       &W[(size_t)(h0 + (n >> 1)) * D_SZ + k0 + q * 8]);
        }
    };

    float acc[4][4][4];
    #pragma unroll
    for (int i = 0; i < 4; i++)
        #pragma unroll
        for (int j = 0; j < 4; j++)
            #pragma unroll
            for (int t = 0; t < 4; t++)
                acc[i][j][t] = 0.0f;

    load_chunk(0, 0); CP_COMMIT();
    load_chunk(1, 1); CP_COMMIT();

    for (int i = 0; i < NCHUNK; i++) {
        if (i == NCHUNK - 1) { CP_WAIT(0); } else { CP_WAIT(1); }
        __syncthreads();
        if (i + 2 < NCHUNK) { load_chunk(i + 2, (i + 2) % STAGES); CP_COMMIT(); }

        const uint32_t sbase = smem_b + (uint32_t)(i % STAGES) * STAGE_WORDS * 4;

        #pragma unroll
        for (int ks = 0; ks < 4; ks++) {
            const uint32_t koff = (uint32_t)ks * 32;   // 8 words = 32B per k16 step
            uint32_t af[4][4], bf[2][4];
            #pragma unroll
            for (int mi = 0; mi < 4; mi++)
                ldsm_x4(af[mi][0], af[mi][1], af[mi][2], af[mi][3],
                        sbase + aLane + (uint32_t)mi * 16 * PITCHB + koff);
            #pragma unroll
            for (int p = 0; p < 2; p++)
                ldsm_x4(bf[p][0], bf[p][1], bf[p][2], bf[p][3],
                        sbase + bLane + (uint32_t)p * 16 * PITCHB + koff);
            #pragma unroll
            for (int mi = 0; mi < 4; mi++) {
                #pragma unroll
                for (int p = 0; p < 2; p++) {
                    mma_f16(acc[mi][2*p  ][0], acc[mi][2*p  ][1],
                            acc[mi][2*p  ][2], acc[mi][2*p  ][3],
                            af[mi][0], af[mi][1], af[mi][2], af[mi][3],
                            bf[p][0], bf[p][1]);
                    mma_f16(acc[mi][2*p+1][0], acc[mi][2*p+1][1],
                            acc[mi][2*p+1][2], acc[mi][2*p+1][3],
                            af[mi][0], af[mi][1], af[mi][2], af[mi][3],
                            bf[p][2], bf[p][3]);
                }
            }
        }
        __syncthreads();
    }

    // ---- epilogue: gates in registers, scalar stores
    #pragma unroll
    for (int mi = 0; mi < 4; mi++) {
        #pragma unroll
        for (int nj = 0; nj < 4; nj++) {
            const int h = h0 + wn * 16 + nj * 4 + gc;
            const float bzv = __ldg(&bz[h]);
            const float bhv = __ldg(&bh[h]);
            #pragma unroll
            for (int half = 0; half < 2; half++) {
                const int m = m0 + wm * 64 + mi * 16 + gr + half * 8;
                float k  = acc[mi][nj][half * 2 + 0] + bzv;
                float th = acc[mi][nj][half * 2 + 1] + bhv;
                float em  = __expf(-fabsf(k));
                float inv = 1.0f / (1.0f + em);
                float z, a;
                if (k >= 0.0f) { z = inv;      a = em * inv; }
                else           { z = em * inv; a = inv;      }
                float g;
                if (th >= 0.0f) g = th + 0.5f;
                else            g = 1.0f / (1.0f + __expf(-th));
                g_k [(size_t)m * H_SZ + h] = a;
                g_th[(size_t)m * H_SZ + h] = z * g;
            }
        }
    }
}

// ===========================================================================
// Chunked scan: h[t] = a[t]*h[t-1] + b[t], h[-1] = 0
// ===========================================================================
__global__ __launch_bounds__(256) void scan1_kernel()
{
    int idx = blockIdx.x * 256 + threadIdx.x;   // 0 .. B*NC*H-1
    int h  = idx & (H_SZ - 1);
    int bc = idx >> 10;
    int c  = bc & (NC - 1);
    int b  = bc >> 5;
    size_t base = ((size_t)b * T_SZ + (size_t)c * CL) * H_SZ + h;

    float A = 1.0f, acc = 0.0f;
    #pragma unroll 4
    for (int t = 0; t < CL; t++) {
        float a  = g_k [base + (size_t)t * H_SZ];
        float bb = g_th[base + (size_t)t * H_SZ];
        A *= a;
        acc = fmaf(a, acc, bb);
    }
    g_A [idx] = A;
    g_Bc[idx] = acc;
}

__global__ __launch_bounds__(256) void scan2_kernel()
{
    int idx = blockIdx.x * 256 + threadIdx.x;   // 0 .. B*H-1
    int h = idx & (H_SZ - 1);
    int b = idx >> 10;
    float carry = 0.0f;
    #pragma unroll
    for (int c = 0; c < NC; c++) {
        int j = (b * NC + c) * H_SZ + h;
        g_hini[j] = carry;
        carry = fmaf(g_A[j], carry, g_Bc[j]);
    }
}

__global__ __launch_bounds__(256) void scan3_kernel(float* __restrict__ out)
{
    int idx = blockIdx.x * 256 + threadIdx.x;
    int h  = idx & (H_SZ - 1);
    int bc = idx >> 10;
    int c  = bc & (NC - 1);
    int b  = bc >> 5;
    size_t base = ((size_t)b * T_SZ + (size_t)c * CL) * H_SZ + h;

    float acc = g_hini[idx];
    #pragma unroll 4
    for (int t = 0; t < CL; t++) {
        float a  = g_k [base + (size_t)t * H_SZ];
        float bb = g_th[base + (size_t)t * H_SZ];
        acc = fmaf(a, acc, bb);
        out[base + (size_t)t * H_SZ] = acc;
    }
}

// ===========================================================================
extern "C" void kernel_launch(void* const* d_in, const int* in_sizes, int n_in,
                              void* d_out, int out_size)
{
    const float* x  = (const float*)d_in[0];
    const float* Wz = (const float*)d_in[1];
    const float* bz = (const float*)d_in[2];
    const float* Wh = (const float*)d_in[3];
    const float* bh = (const float*)d_in[4];
    float* out = (float*)d_out;

    cudaFuncSetAttribute(gemm_kernel,
                         cudaFuncAttributeMaxDynamicSharedMemorySize, SMEM_DYN);

    // fp32 -> fp16 conversion
    __half* xh;  cudaGetSymbolAddress((void**)&xh,  g_xh);
    __half* wzh; cudaGetSymbolAddress((void**)&wzh, g_wzh);
    __half* whh; cudaGetSymbolAddress((void**)&whh, g_whh);
    cvt_kernel<<<(M_TOT * D_SZ) / (256 * 8), 256>>>(x,  xh);
    cvt_kernel<<<(H_SZ * D_SZ) / (256 * 8), 256>>>(Wz, wzh);
    cvt_kernel<<<(H_SZ * D_SZ) / (256 * 8), 256>>>(Wh, whh);

    dim3 ggrid(H_SZ / (BN / 2), M_TOT / BM);   // (8, 256)
    gemm_kernel<<<ggrid, 512, SMEM_DYN>>>(bz, bh);

    scan1_kernel<<<(B_SZ * NC * H_SZ) / 256, 256>>>();
    scan2_kernel<<<(B_SZ * H_SZ) / 256, 256>>>();
    scan3_kernel<<<(B_SZ * NC * H_SZ) / 256, 256>>>(out);
}

// round 8
// speedup vs baseline: 3.7626x; 1.0821x over previous
#include <cuda_runtime.h>
#include <cuda_fp16.h>
#include <cstdint>

#define B_SZ 8
#define T_SZ 4096
#define D_SZ 1024
#define H_SZ 1024
#define M_TOT (B_SZ * T_SZ)   // 32768
#define NC 32                  // chunks along T (scan)
#define CL 128                 // chunk length (NC*CL = T_SZ)

// Scratch (static __device__ arrays — no allocation in kernel_launch)
__device__ float g_k [M_TOT * H_SZ];   // a = sigmoid(-k)
__device__ float g_th[M_TOT * H_SZ];   // b = sigmoid(k)*g(th)
__device__ float g_A   [B_SZ * NC * H_SZ];
__device__ float g_Bc  [B_SZ * NC * H_SZ];
__device__ float g_hini[B_SZ * NC * H_SZ];
__device__ __half g_xh [M_TOT * D_SZ];  // fp16 copies for tensor path
__device__ __half g_wzh[H_SZ * D_SZ];
__device__ __half g_whh[H_SZ * D_SZ];

// ===========================================================================
// Helpers
// ===========================================================================
__device__ __forceinline__ uint32_t smem_u32(const void* p) {
    uint32_t a;
    asm("{ .reg .u64 t; cvta.to.shared.u64 t, %1; cvt.u32.u64 %0, t; }" : "=r"(a) : "l"(p));
    return a;
}
__device__ __forceinline__ void cp_async16(uint32_t dst, const void* src) {
    asm volatile("cp.async.cg.shared.global [%0], [%1], 16;\n" :: "r"(dst), "l"(src));
}
#define CP_COMMIT() asm volatile("cp.async.commit_group;\n" ::: "memory")
#define CP_WAIT(N)  asm volatile("cp.async.wait_group %0;\n" :: "n"(N) : "memory")

__device__ __forceinline__ void ldsm_x4(uint32_t& r0, uint32_t& r1,
                                        uint32_t& r2, uint32_t& r3, uint32_t addr) {
    asm volatile("ldmatrix.sync.aligned.m8n8.x4.shared.b16 {%0,%1,%2,%3}, [%4];"
                 : "=r"(r0), "=r"(r1), "=r"(r2), "=r"(r3) : "r"(addr));
}

__device__ __forceinline__ void mma_f16(float& c0, float& c1, float& c2, float& c3,
                                        uint32_t a0, uint32_t a1, uint32_t a2, uint32_t a3,
                                        uint32_t b0, uint32_t b1) {
    asm volatile(
        "mma.sync.aligned.m16n8k16.row.col.f32.f16.f16.f32 "
        "{%0,%1,%2,%3}, {%4,%5,%6,%7}, {%8,%9}, {%0,%1,%2,%3};"
        : "+f"(c0), "+f"(c1), "+f"(c2), "+f"(c3)
        : "r"(a0), "r"(a1), "r"(a2), "r"(a3), "r"(b0), "r"(b1));
}

// ===========================================================================
// fp32 -> fp16 conversion pass (8 elems/thread, vectorized)
// ===========================================================================
__global__ __launch_bounds__(256) void cvt_kernel(const float* __restrict__ src,
                                                  __half* __restrict__ dst)
{
    size_t i = ((size_t)blockIdx.x * 256 + threadIdx.x) * 8;
    float4 v0 = *reinterpret_cast<const float4*>(src + i);
    float4 v1 = *reinterpret_cast<const float4*>(src + i + 4);
    __half2 h[4];
    h[0] = __floats2half2_rn(v0.x, v0.y);
    h[1] = __floats2half2_rn(v0.z, v0.w);
    h[2] = __floats2half2_rn(v1.x, v1.y);
    h[3] = __floats2half2_rn(v1.z, v1.w);
    *reinterpret_cast<uint4*>(dst + i) = *reinterpret_cast<uint4*>(h);
}

// ===========================================================================
// Fused GEMM (mma.sync fp16, fp32 accum, ldmatrix) + bias + gate epilogue.
// 256 threads = 8 warps: 2 warp-rows (64 M) x 4 warp-cols (32 N).
// CTA tile M=128 x N=128 (64 h); N interleaves (Wz,Wh): even->k, odd->th.
// 2 CTAs/SM for cross-CTA latency hiding; single barrier per K-chunk.
// ===========================================================================
#define BM 128
#define BN 128
#define BK 64                           // halfs per chunk = 4 x k16 steps
#define STAGES 3
#define PITCHW 36                       // 32-bit words per smem row
#define PITCHB (PITCHW * 4)             // 144 bytes
#define A_WORDS (BM * PITCHW)           // 4608
#define B_WORDS (BN * PITCHW)           // 4608
#define STAGE_WORDS (A_WORDS + B_WORDS) // 9216
#define SMEM_DYN (STAGES * STAGE_WORDS * 4)   // 110592 bytes
#define NCHUNK (D_SZ / BK)              // 16

__global__ void __launch_bounds__(256, 2)
gemm_kernel(const float* __restrict__ bz,
            const float* __restrict__ bh)
{
    extern __shared__ uint32_t smem[];
    const uint32_t smem_b = smem_u32(smem);

    const int tid = threadIdx.x;
    const int wid = tid >> 5;
    const int lid = tid & 31;
    const int gr  = lid >> 2;    // 0..7
    const int gc  = lid & 3;     // 0..3
    const int wm  = wid & 1;     // 2 warp rows (64 M each)
    const int wn  = wid >> 1;    // 4 warp cols (32 N each)
    const int m0  = blockIdx.y * BM;
    const int h0  = blockIdx.x * (BN / 2);   // 64 h per CTA

    // ---- per-lane ldmatrix byte offsets (within a stage)
    const uint32_t aLane = (uint32_t)(wm * 64 + (lid & 15)) * PITCHB + (uint32_t)(lid >> 4) * 16;
    const uint32_t bLane = A_WORDS * 4
        + (uint32_t)(wn * 32 + ((lid >> 4) & 1) * 8 + (lid & 7)) * PITCHB
        + (uint32_t)((lid >> 3) & 1) * 16;

    // ---- async loader: one K-chunk (64 halfs = 128B/row) into stage s
    auto load_chunk = [&](int c, int s) {
        const int k0 = c * BK;
        const uint32_t abase = smem_b + (uint32_t)s * STAGE_WORDS * 4;
        const uint32_t bbase = abase + A_WORDS * 4;
        // A: 128 rows x 8 x 16B = 1024 -> 4/thread
        #pragma unroll
        for (int j = 0; j < 4; j++) {
            int idx = tid + j * 256;
            int r = idx >> 3, q = idx & 7;
            cp_async16(abase + r * PITCHB + q * 16,
                       &g_xh[(size_t)(m0 + r) * D_SZ + k0 + q * 8]);
        }
        // B: 128 rows x 8 x 16B = 1024 -> 4/thread (interleaved Wz/Wh)
        #pragma unroll
        for (int j = 0; j < 4; j++) {
            int idx = tid + j * 256;
            int n = idx >> 3, q = idx & 7;
            const __half* W = (n & 1) ? g_whh : g_wzh;
            cp_async16(bbase + n * PITCHB + q * 16,
                       &W[(size_t)(h0 + (n >> 1)) * D_SZ + k0 + q * 8]);
        }
    };

    float acc[4][4][4];
    #pragma unroll
    for (int i = 0; i < 4; i++)
        #pragma unroll
        for (int j = 0; j < 4; j++)
            #pragma unroll
            for (int t = 0; t < 4; t++)
                acc[i][j][t] = 0.0f;

    load_chunk(0, 0); CP_COMMIT();
    load_chunk(1, 1); CP_COMMIT();

    for (int i = 0; i < NCHUNK; i++) {
        if (i == NCHUNK - 1) { CP_WAIT(0); } else { CP_WAIT(1); }
        // Single barrier: makes chunk i visible AND certifies all warps are
        // done with chunk i-1, so its stage (== (i+2)%3) may be overwritten.
        __syncthreads();
        if (i + 2 < NCHUNK) { load_chunk(i + 2, (i + 2) % STAGES); CP_COMMIT(); }

        const uint32_t sbase = smem_b + (uint32_t)(i % STAGES) * STAGE_WORDS * 4;

        #pragma unroll
        for (int ks = 0; ks < 4; ks++) {
            const uint32_t koff = (uint32_t)ks * 32;   // 8 words = 32B per k16 step
            uint32_t af[4][4], bf[2][4];
            #pragma unroll
            for (int mi = 0; mi < 4; mi++)
                ldsm_x4(af[mi][0], af[mi][1], af[mi][2], af[mi][3],
                        sbase + aLane + (uint32_t)mi * 16 * PITCHB + koff);
            #pragma unroll
            for (int p = 0; p < 2; p++)
                ldsm_x4(bf[p][0], bf[p][1], bf[p][2], bf[p][3],
                        sbase + bLane + (uint32_t)p * 16 * PITCHB + koff);
            #pragma unroll
            for (int mi = 0; mi < 4; mi++) {
                #pragma unroll
                for (int p = 0; p < 2; p++) {
                    mma_f16(acc[mi][2*p  ][0], acc[mi][2*p  ][1],
                            acc[mi][2*p  ][2], acc[mi][2*p  ][3],
                            af[mi][0], af[mi][1], af[mi][2], af[mi][3],
                            bf[p][0], bf[p][1]);
                    mma_f16(acc[mi][2*p+1][0], acc[mi][2*p+1][1],
                            acc[mi][2*p+1][2], acc[mi][2*p+1][3],
                            af[mi][0], af[mi][1], af[mi][2], af[mi][3],
                            bf[p][2], bf[p][3]);
                }
            }
        }
    }

    // ---- epilogue: gates in registers, scalar stores
    #pragma unroll
    for (int mi = 0; mi < 4; mi++) {
        #pragma unroll
        for (int nj = 0; nj < 4; nj++) {
            const int h = h0 + wn * 16 + nj * 4 + gc;
            const float bzv = __ldg(&bz[h]);
            const float bhv = __ldg(&bh[h]);
            #pragma unroll
            for (int half = 0; half < 2; half++) {
                const int m = m0 + wm * 64 + mi * 16 + gr + half * 8;
                float k  = acc[mi][nj][half * 2 + 0] + bzv;
                float th = acc[mi][nj][half * 2 + 1] + bhv;
                float em  = __expf(-fabsf(k));
                float inv = 1.0f / (1.0f + em);
                float z, a;
                if (k >= 0.0f) { z = inv;      a = em * inv; }
                else           { z = em * inv; a = inv;      }
                float g;
                if (th >= 0.0f) g = th + 0.5f;
                else            g = 1.0f / (1.0f + __expf(-th));
                g_k [(size_t)m * H_SZ + h] = a;
                g_th[(size_t)m * H_SZ + h] = z * g;
            }
        }
    }
}

// ===========================================================================
// Chunked scan: h[t] = a[t]*h[t-1] + b[t], h[-1] = 0
// ===========================================================================
__global__ __launch_bounds__(256) void scan1_kernel()
{
    int idx = blockIdx.x * 256 + threadIdx.x;   // 0 .. B*NC*H-1
    int h  = idx & (H_SZ - 1);
    int bc = idx >> 10;
    int c  = bc & (NC - 1);
    int b  = bc >> 5;
    size_t base = ((size_t)b * T_SZ + (size_t)c * CL) * H_SZ + h;

    float A = 1.0f, acc = 0.0f;
    #pragma unroll 4
    for (int t = 0; t < CL; t++) {
        float a  = g_k [base + (size_t)t * H_SZ];
        float bb = g_th[base + (size_t)t * H_SZ];
        A *= a;
        acc = fmaf(a, acc, bb);
    }
    g_A [idx] = A;
    g_Bc[idx] = acc;
}

__global__ __launch_bounds__(256) void scan2_kernel()
{
    int idx = blockIdx.x * 256 + threadIdx.x;   // 0 .. B*H-1
    int h = idx & (H_SZ - 1);
    int b = idx >> 10;
    float carry = 0.0f;
    #pragma unroll
    for (int c = 0; c < NC; c++) {
        int j = (b * NC + c) * H_SZ + h;
        g_hini[j] = carry;
        carry = fmaf(g_A[j], carry, g_Bc[j]);
    }
}

__global__ __launch_bounds__(256) void scan3_kernel(float* __restrict__ out)
{
    int idx = blockIdx.x * 256 + threadIdx.x;
    int h  = idx & (H_SZ - 1);
    int bc = idx >> 10;
    int c  = bc & (NC - 1);
    int b  = bc >> 5;
    size_t base = ((size_t)b * T_SZ + (size_t)c * CL) * H_SZ + h;

    float acc = g_hini[idx];
    #pragma unroll 4
    for (int t = 0; t < CL; t++) {
        float a  = g_k [base + (size_t)t * H_SZ];
        float bb = g_th[base + (size_t)t * H_SZ];
        acc = fmaf(a, acc, bb);
        out[base + (size_t)t * H_SZ] = acc;
    }
}

// ===========================================================================
extern "C" void kernel_launch(void* const* d_in, const int* in_sizes, int n_in,
                              void* d_out, int out_size)
{
    const float* x  = (const float*)d_in[0];
    const float* Wz = (const float*)d_in[1];
    const float* bz = (const float*)d_in[2];
    const float* Wh = (const float*)d_in[3];
    const float* bh = (const float*)d_in[4];
    float* out = (float*)d_out;

    cudaFuncSetAttribute(gemm_kernel,
                         cudaFuncAttributeMaxDynamicSharedMemorySize, SMEM_DYN);

    // fp32 -> fp16 conversion
    __half* xh;  cudaGetSymbolAddress((void**)&xh,  g_xh);
    __half* wzh; cudaGetSymbolAddress((void**)&wzh, g_wzh);
    __half* whh; cudaGetSymbolAddress((void**)&whh, g_whh);
    cvt_kernel<<<(M_TOT * D_SZ) / (256 * 8), 256>>>(x,  xh);
    cvt_kernel<<<(H_SZ * D_SZ) / (256 * 8), 256>>>(Wz, wzh);
    cvt_kernel<<<(H_SZ * D_SZ) / (256 * 8), 256>>>(Wh, whh);

    dim3 ggrid(H_SZ / (BN / 2), M_TOT / BM);   // (16, 256)
    gemm_kernel<<<ggrid, 256, SMEM_DYN>>>(bz, bh);

    scan1_kernel<<<(B_SZ * NC * H_SZ) / 256, 256>>>();
    scan2_kernel<<<(B_SZ * H_SZ) / 256, 256>>>();
    scan3_kernel<<<(B_SZ * NC * H_SZ) / 256, 256>>>(out);
}